// round 4
// baseline (speedup 1.0000x reference)
#include <cuda_runtime.h>

#define C_ATOM 128
#define C_REF  389
#define C_PAIR 16
#define CL_ROWS   8      // rows per cl chunk
#define CL_D      4      // plm-unit equivalents charged to a cl block
#define BLK_PER_SM 6

// ---------------------------------------------------------------------------
// One persistent-wave fused kernel.
//
// Work model: plm is decomposed into "units" of 64 consecutive m for one l.
//   unit u: l = u / (N/64), j = u % (N/64), pairs (l, j*64 .. j*64+63).
//   256 threads, 4 threads per pair -> each thread stores one float4;
//   unit stores 4 KB contiguous at plm_base + u*1024 floats.
// Blocks get contiguous unit ranges via a weighted balanced partition:
//   virtual total V = TU + 256*CL_D; cl blocks (b < 256) are charged CL_D.
// cl: chunk b = rows [8b, 8b+8); warp owns a row, lane owns 4 channels
//   (float4 W loads, 512B/warp coalesced), feature row staged in shared.
// ---------------------------------------------------------------------------
__global__ void __launch_bounds__(256, BLK_PER_SM)
fused_kernel(const float* __restrict__ pos,
             const float* __restrict__ charge,
             const float* __restrict__ mask,
             const float* __restrict__ elem,
             const float* __restrict__ names,
             const int*   __restrict__ uid,
             const float* __restrict__ Wf,
             const float* __restrict__ bf,
             const float* __restrict__ Woff,
             const float* __restrict__ boff,
             const float* __restrict__ Winv,
             const float* __restrict__ binv,
             const float* __restrict__ Wvm,
             const float* __restrict__ bvm,
             float* __restrict__ out, int N, int clChunks)
{
    __shared__ float sf[CL_ROWS][C_REF];

    const int b   = blockIdx.x;
    const int tid = threadIdx.x;
    const int G   = gridDim.x;

    // ------------------------- cl (first clChunks blocks) -------------------
    if (b < clChunks) {
        const int n0   = b * CL_ROWS;
        const int warp = tid >> 5;
        const int lane = tid & 31;

        for (int idx = tid; idx < CL_ROWS * C_REF; idx += 256) {
            int r = idx / C_REF;
            int j = idx - r * C_REF;
            int n = n0 + r;
            float v;
            if (j < 3)        v = pos[n * 3 + j];
            else if (j == 3)  v = charge[n];
            else if (j == 4)  v = mask[n];
            else if (j < 133) v = elem[n * 128 + (j - 5)];
            else              v = names[n * 256 + (j - 133)];
            sf[r][j] = v;
        }
        __syncthreads();

        const int c4 = lane * 4;
        float4 acc = *reinterpret_cast<const float4*>(bf + c4);

#pragma unroll 4
        for (int j = 0; j < C_REF; j++) {
            float4 w = *reinterpret_cast<const float4*>(Wf + j * C_ATOM + c4);
            float  f = sf[warp][j];
            acc.x = fmaf(w.x, f, acc.x);
            acc.y = fmaf(w.y, f, acc.y);
            acc.z = fmaf(w.z, f, acc.z);
            acc.w = fmaf(w.w, f, acc.w);
        }
        *reinterpret_cast<float4*>(out + (long long)(n0 + warp) * C_ATOM + c4) = acc;
    }

    // ------------------------------- plm ------------------------------------
    const int       mchunks = N >> 6;                       // units per l row
    const long long TU      = (long long)N * mchunks;      // total units
    const long long V       = TU + (long long)clChunks * CL_D;

    const long long vs = (long long)b * V / G;
    const long long ve = (long long)(b + 1) * V / G;
    const int c0 = (b     < clChunks) ? b     : clChunks;
    const int c1 = (b + 1 < clChunks) ? b + 1 : clChunks;
    long long u  = vs - (long long)CL_D * c0;
    const long long re = ve - (long long)CL_D * c1;
    if (u >= re) return;

    const int pair = tid >> 2;           // 0..63
    const int kg   = (tid & 3) * 4;      // 0,4,8,12

    // Coefficients in registers.
    const float4 w0 = *reinterpret_cast<const float4*>(Woff + kg);
    const float4 w1 = *reinterpret_cast<const float4*>(Woff + C_PAIR + kg);
    const float4 w2 = *reinterpret_cast<const float4*>(Woff + 2 * C_PAIR + kg);
    const float4 wi = *reinterpret_cast<const float4*>(Winv + kg);
    float4 cb;
    {
        const float4 t1 = *reinterpret_cast<const float4*>(boff + kg);
        const float4 t2 = *reinterpret_cast<const float4*>(binv + kg);
        const float4 t3 = *reinterpret_cast<const float4*>(Wvm + kg);
        const float4 t4 = *reinterpret_cast<const float4*>(bvm + kg);
        cb.x = t1.x + t2.x + t3.x + t4.x;
        cb.y = t1.y + t2.y + t3.y + t4.y;
        cb.z = t1.z + t2.z + t3.z + t4.z;
        cb.w = t1.w + t2.w + t3.w + t4.w;
    }

    int l = (int)(u / mchunks);
    int j = (int)(u - (long long)l * mchunks);

    float* base = out + (long long)N * C_ATOM + tid * 4;

    // Software-pipelined uid loads.
    int um = __ldg(uid + j * 64 + pair);
    int ul = __ldg(uid + l);

    for (; u < re; u++) {
        // prefetch next unit's uids (clamped to stay in-bounds)
        int jn = j + 1;
        int ln = l;
        if (jn == mchunks) { jn = 0; ln = l + 1; }
        int lnc = (ln < N) ? ln : N - 1;
        const int um_n = __ldg(uid + jn * 64 + pair);
        const int ul_n = __ldg(uid + lnc);

        float4 r;
        if (um == ul) {
            // Rare path (~0.4% of pairs): full affine map.
            const float d0 = __ldg(pos + l * 3 + 0) - __ldg(pos + (j * 64 + pair) * 3 + 0);
            const float d1 = __ldg(pos + l * 3 + 1) - __ldg(pos + (j * 64 + pair) * 3 + 1);
            const float d2 = __ldg(pos + l * 3 + 2) - __ldg(pos + (j * 64 + pair) * 3 + 2);
            float s = fmaf(d0, d0, 1.0f);
            s = fmaf(d1, d1, s);
            s = fmaf(d2, d2, s);
            const float inv = __fdividef(1.0f, s);

            r.x = fmaf(d0, w0.x, cb.x); r.y = fmaf(d0, w0.y, cb.y);
            r.z = fmaf(d0, w0.z, cb.z); r.w = fmaf(d0, w0.w, cb.w);
            r.x = fmaf(d1, w1.x, r.x);  r.y = fmaf(d1, w1.y, r.y);
            r.z = fmaf(d1, w1.z, r.z);  r.w = fmaf(d1, w1.w, r.w);
            r.x = fmaf(d2, w2.x, r.x);  r.y = fmaf(d2, w2.y, r.y);
            r.z = fmaf(d2, w2.z, r.z);  r.w = fmaf(d2, w2.w, r.w);
            r.x = fmaf(inv, wi.x, r.x); r.y = fmaf(inv, wi.y, r.y);
            r.z = fmaf(inv, wi.z, r.z); r.w = fmaf(inv, wi.w, r.w);
        } else {
            r = make_float4(0.f, 0.f, 0.f, 0.f);
        }
        __stcs(reinterpret_cast<float4*>(base + u * (64 * C_PAIR)), r);

        um = um_n; ul = ul_n; j = jn; l = ln;
    }
}

// ---------------------------------------------------------------------------
// Launch: one kernel, one wave (SMs * BLK_PER_SM blocks).
// ---------------------------------------------------------------------------
extern "C" void kernel_launch(void* const* d_in, const int* in_sizes, int n_in,
                              void* d_out, int out_size)
{
    const float* pos    = (const float*)d_in[0];
    const float* charge = (const float*)d_in[1];
    const float* maskp  = (const float*)d_in[2];
    const float* elem   = (const float*)d_in[3];
    const float* names  = (const float*)d_in[4];
    const int*   uid    = (const int*)  d_in[5];
    const float* Wf     = (const float*)d_in[6];
    const float* bf     = (const float*)d_in[7];
    const float* Woff   = (const float*)d_in[8];
    const float* boff   = (const float*)d_in[9];
    const float* Winv   = (const float*)d_in[10];
    const float* binv   = (const float*)d_in[11];
    const float* Wvm    = (const float*)d_in[12];
    const float* bvm    = (const float*)d_in[13];

    const int N = in_sizes[1];  // B*N with B=1
    float* out = (float*)d_out;

    int nsm = 148;
    cudaDeviceGetAttribute(&nsm, cudaDevAttrMultiProcessorCount, 0);

    const int clChunks = N / CL_ROWS;          // 256
    int grid = nsm * BLK_PER_SM;               // single wave
    if (grid < clChunks) grid = clChunks;      // safety for cl coverage

    fused_kernel<<<grid, 256>>>(
        pos, charge, maskp, elem, names, uid, Wf, bf,
        Woff, boff, Winv, binv, Wvm, bvm, out, N, clChunks);
}